// round 13
// baseline (speedup 1.0000x reference)
#include <cuda_runtime.h>
#include <cuda_bf16.h>
#include <cuda_fp16.h>
#include <cstdint>
#include <math.h>

#define BB   16
#define SQL  2048
#define SKL  2048
#define DD   128
#define NROWS (BB * SQL)
#define NTILES 16

// ---------------- scratch (__device__ globals; no allocation) ----------------
__device__ __nv_bfloat16 g_Qh[(size_t)BB * SQL * DD];
__device__ __nv_bfloat16 g_Ql[(size_t)BB * SQL * DD];
__device__ __nv_bfloat16 g_Kh[(size_t)BB * SKL * DD];
__device__ __nv_bfloat16 g_Kl[(size_t)BB * SKL * DD];
__device__ __half g_Vth[(size_t)BB * DD * SKL];          // V^T hi (fp16)
__device__ __half g_Vtl[(size_t)BB * DD * SKL];          // V^T lo (fp16)
__device__ __half g_Ef[(size_t)NROWS * SKL];             // exp (fp16)
__device__ float g_ps[(size_t)NROWS * NTILES];           // per-(row,ktile) sum exp
__device__ uint32_t g_mbits[(size_t)NROWS * (SKL / 32)]; // packed mask bits

// ---------------- helpers ----------------------------------------------------
__device__ __forceinline__ uint32_t pack2_hi(float a, float b, float& la, float& lb) {
    __nv_bfloat16 ha = __float2bfloat16_rn(a), hb = __float2bfloat16_rn(b);
    la = a - __bfloat162float(ha);
    lb = b - __bfloat162float(hb);
    return (uint32_t)__bfloat16_as_ushort(ha) | ((uint32_t)__bfloat16_as_ushort(hb) << 16);
}
__device__ __forceinline__ uint32_t pack2(float a, float b) {
    __nv_bfloat16 ha = __float2bfloat16_rn(a), hb = __float2bfloat16_rn(b);
    return (uint32_t)__bfloat16_as_ushort(ha) | ((uint32_t)__bfloat16_as_ushort(hb) << 16);
}
__device__ __forceinline__ uint32_t pack2h_hi(float a, float b, float& la, float& lb) {
    __half ha = __float2half_rn(a), hb = __float2half_rn(b);
    la = a - __half2float(ha);
    lb = b - __half2float(hb);
    return (uint32_t)__half_as_ushort(ha) | ((uint32_t)__half_as_ushort(hb) << 16);
}
__device__ __forceinline__ uint32_t pack2h(float a, float b) {
    __half ha = __float2half_rn(a), hb = __float2half_rn(b);
    return (uint32_t)__half_as_ushort(ha) | ((uint32_t)__half_as_ushort(hb) << 16);
}
__device__ __forceinline__ float2 unpack2h(uint32_t u) {
    __half2 v = *reinterpret_cast<__half2*>(&u);
    return make_float2(__half2float(v.x), __half2float(v.y));
}
__device__ __forceinline__ void mma_bf16(float* c, uint32_t a0, uint32_t a1,
                                         uint32_t a2, uint32_t a3,
                                         uint32_t b0, uint32_t b1) {
    asm volatile(
        "mma.sync.aligned.m16n8k16.row.col.f32.bf16.bf16.f32 "
        "{%0,%1,%2,%3}, {%4,%5,%6,%7}, {%8,%9}, {%0,%1,%2,%3};"
        : "+f"(c[0]), "+f"(c[1]), "+f"(c[2]), "+f"(c[3])
        : "r"(a0), "r"(a1), "r"(a2), "r"(a3), "r"(b0), "r"(b1));
}
__device__ __forceinline__ void mma_f16(float* c, uint32_t a0, uint32_t a1,
                                        uint32_t a2, uint32_t a3,
                                        uint32_t b0, uint32_t b1) {
    asm volatile(
        "mma.sync.aligned.m16n8k16.row.col.f32.f16.f16.f32 "
        "{%0,%1,%2,%3}, {%4,%5,%6,%7}, {%8,%9}, {%0,%1,%2,%3};"
        : "+f"(c[0]), "+f"(c[1]), "+f"(c[2]), "+f"(c[3])
        : "r"(a0), "r"(a1), "r"(a2), "r"(a3), "r"(b0), "r"(b1));
}
__device__ __forceinline__ void ldsm4(uint32_t& r0, uint32_t& r1, uint32_t& r2,
                                      uint32_t& r3, uint32_t addr) {
    asm volatile("ldmatrix.sync.aligned.m8n8.x4.shared.b16 {%0,%1,%2,%3}, [%4];"
                 : "=r"(r0), "=r"(r1), "=r"(r2), "=r"(r3) : "r"(addr));
}
__device__ __forceinline__ void cpa16(uint32_t dst, const void* src) {
    asm volatile("cp.async.cg.shared.global [%0], [%1], 16;" :: "r"(dst), "l"(src));
}
#define CP_COMMIT() asm volatile("cp.async.commit_group;" ::: "memory")
#define CP_WAIT0()  asm volatile("cp.async.wait_group 0;" ::: "memory")
#define CP_WAIT1()  asm volatile("cp.async.wait_group 1;" ::: "memory")
#define CP_WAIT2()  asm volatile("cp.async.wait_group 2;" ::: "memory")

// tile geometry: 128 rows x 32 cols (2B elems), row stride 80 bytes
#define TW 80
#define TT (128 * TW)                   // 10240 per tile
#define BUFB (4 * TT)                   // qk: 4-tile buffer
#define BUFB3 (3 * TT)                  // pv: 3-tile buffer (E, Vh, Vl)
#define STASHW 132
#define DYN_QK (2 * BUFB)               // 81920
#define DYN_PV (3 * BUFB3 + 512)        // 92672 (3-stage pipeline)

// ---------------------------------------------------------------------------
// prep: split fp32 rows of Q and K into hi/lo bf16 (row-major, linear)
// ---------------------------------------------------------------------------
__global__ __launch_bounds__(256) void prep_qk_kernel(const float* __restrict__ Q,
                                                      const float* __restrict__ K) {
    const float* src = blockIdx.y ? K : Q;
    __nv_bfloat16* dh = blockIdx.y ? g_Kh : g_Qh;
    __nv_bfloat16* dl = blockIdx.y ? g_Kl : g_Ql;
    size_t idx = (size_t)blockIdx.x * 256 + threadIdx.x;
    const float* p = src + idx * 8;
    float4 f0 = *(const float4*)p, f1 = *(const float4*)(p + 4);
    float l[8];
    uint4 hv, lv;
    hv.x = pack2_hi(f0.x, f0.y, l[0], l[1]);
    hv.y = pack2_hi(f0.z, f0.w, l[2], l[3]);
    hv.z = pack2_hi(f1.x, f1.y, l[4], l[5]);
    hv.w = pack2_hi(f1.z, f1.w, l[6], l[7]);
    lv.x = pack2(l[0], l[1]); lv.y = pack2(l[2], l[3]);
    lv.z = pack2(l[4], l[5]); lv.w = pack2(l[6], l[7]);
    *(uint4*)(dh + idx * 8) = hv;
    *(uint4*)(dl + idx * 8) = lv;
}

// prep: V^T fp16 hi/lo: [b][dv][k]
__global__ __launch_bounds__(256) void prep_vt_kernel(const float* __restrict__ V) {
    int chunk = blockIdx.x, b = blockIdx.y, tid = threadIdx.x;
#pragma unroll
    for (int g = 0; g < 8; g++) {
        int item = tid + g * 256;
        int r = item & 127;           // n (dv)
        int c8 = item >> 7;           // k-group
        int k0 = chunk * 128 + c8 * 8;
        float f[8], l[8];
#pragma unroll
        for (int j = 0; j < 8; j++)
            f[j] = V[((size_t)b * SKL + k0 + j) * DD + r];
        uint4 hv, lv;
        hv.x = pack2h_hi(f[0], f[1], l[0], l[1]);
        hv.y = pack2h_hi(f[2], f[3], l[2], l[3]);
        hv.z = pack2h_hi(f[4], f[5], l[4], l[5]);
        hv.w = pack2h_hi(f[6], f[7], l[6], l[7]);
        lv.x = pack2h(l[0], l[1]); lv.y = pack2h(l[2], l[3]);
        lv.z = pack2h(l[4], l[5]); lv.w = pack2h(l[6], l[7]);
        size_t dst = ((size_t)b * DD + r) * SKL + k0;
        *(uint4*)(g_Vth + dst) = hv;
        *(uint4*)(g_Vtl + dst) = lv;
    }
}

// ---------------------------------------------------------------------------
// prep: pack mask into bits (bit j of word w ~ col w*32+j). One warp per row.
// ---------------------------------------------------------------------------
__global__ __launch_bounds__(256) void prep_mask_kernel(const int* __restrict__ mask) {
    const int wid = threadIdx.x >> 5, lane = threadIdx.x & 31;
    const size_t row = (size_t)blockIdx.x * 8 + wid;
    const int* mrow = mask + row * SKL;
    uint32_t* dst = g_mbits + row * (SKL / 32);
#pragma unroll
    for (int i = 0; i < 16; i++) {
        const int base = i * 128;
        uint32_t b0 = __ballot_sync(0xffffffffu, mrow[base + lane] != 0);
        uint32_t b1 = __ballot_sync(0xffffffffu, mrow[base + 32 + lane] != 0);
        uint32_t b2 = __ballot_sync(0xffffffffu, mrow[base + 64 + lane] != 0);
        uint32_t b3 = __ballot_sync(0xffffffffu, mrow[base + 96 + lane] != 0);
        if (lane == 0)
            *(uint4*)(dst + i * 4) = make_uint4(b0, b1, b2, b3);
    }
}

// ---------------------------------------------------------------------------
// qk: E = exp(scale * Q @ K^T) masked (->0), quantized to fp16; writes E +
// per-(row,ktile) sums of the QUANTIZED values. grid (16,16,16), 256 thr.
// ---------------------------------------------------------------------------
__global__ __launch_bounds__(256, 2) void qk_mma_kernel(float* __restrict__ dummy) {
    extern __shared__ char sm[];
    const uint32_t sb = (uint32_t)__cvta_generic_to_shared(sm);
    const int tid = threadIdx.x, wid = tid >> 5, lane = tid & 31;
    const int wm = wid >> 2, wn = wid & 3;
    const int kt = blockIdx.x, qt = blockIdx.y, b = blockIdx.z;
    const size_t rowbase = (size_t)b * SQL + qt * 128;

    const int la_row = lane & 15;
    const int la_k   = (lane & 16) ? 16 : 0;
    const int lb_row = (lane & 7) + ((lane & 16) ? 8 : 0);
    const int lb_k   = (lane & 8) ? 16 : 0;

    float acc[4][4][4];
#pragma unroll
    for (int mt = 0; mt < 4; mt++)
#pragma unroll
        for (int nt = 0; nt < 4; nt++)
#pragma unroll
            for (int i = 0; i < 4; i++) acc[mt][nt][i] = 0.0f;

    const __nv_bfloat16* srcs[4] = {
        g_Qh + rowbase * DD, g_Ql + rowbase * DD,
        g_Kh + ((size_t)b * SKL + kt * 128) * DD,
        g_Kl + ((size_t)b * SKL + kt * 128) * DD};

    auto qstage = [&](int sl, int st) {
        uint32_t base = sb + (uint32_t)st * BUFB;
#pragma unroll
        for (int t = 0; t < 4; t++) {
            const __nv_bfloat16* sp = srcs[t] + sl * 32;
            uint32_t db = base + t * TT;
#pragma unroll
            for (int g = 0; g < 2; g++) {
                int idx = tid + g * 256;
                int row = idx >> 2, c = idx & 3;
                cpa16(db + row * TW + c * 16, sp + (size_t)row * DD + c * 8);
            }
        }
        CP_COMMIT();
    };

    qstage(0, 0);
#pragma unroll
    for (int sl = 0; sl < 4; sl++) {
        if (sl < 3) { qstage(sl + 1, (sl + 1) & 1); CP_WAIT1(); }
        else        { CP_WAIT0(); }
        __syncthreads();
        const uint32_t base = sb + (uint32_t)(sl & 1) * BUFB;
#pragma unroll
        for (int ks = 0; ks < 2; ks++) {
            const int kb = ks * 32;
            uint32_t bh[4][2], bl[4][2];
#pragma unroll
            for (int ntp = 0; ntp < 2; ntp++) {
                uint32_t ba = base + 2 * TT + (uint32_t)(wn * 32 + ntp * 16 + lb_row) * TW + kb + lb_k;
                ldsm4(bh[2 * ntp][0], bh[2 * ntp][1], bh[2 * ntp + 1][0], bh[2 * ntp + 1][1], ba);
                ldsm4(bl[2 * ntp][0], bl[2 * ntp][1], bl[2 * ntp + 1][0], bl[2 * ntp + 1][1], ba + TT);
            }
#pragma unroll
            for (int mt = 0; mt < 4; mt++) {
                uint32_t aa = base + (uint32_t)(wm * 64 + mt * 16 + la_row) * TW + kb + la_k;
                uint32_t ah0, ah1, ah2, ah3, al0, al1, al2, al3;
                ldsm4(ah0, ah1, ah2, ah3, aa);
                ldsm4(al0, al1, al2, al3, aa + TT);
#pragma unroll
                for (int nt = 0; nt < 4; nt++) {
                    mma_bf16(acc[mt][nt], ah0, ah1, ah2, ah3, bh[nt][0], bh[nt][1]);
                    mma_bf16(acc[mt][nt], al0, al1, al2, al3, bh[nt][0], bh[nt][1]);
                    mma_bf16(acc[mt][nt], ah0, ah1, ah2, ah3, bl[nt][0], bl[nt][1]);
                }
            }
        }
        __syncthreads();
    }

    // epilogue: packed mask bits, exp, fp16 quantize, sums, stash, fp16 write
    float* stashf = (float*)sm;
    float* red2   = (float*)(sm + 128 * STASHW * 4);   // 67584

    const float scale = 0.08838834764831845f;
    const int rq = lane >> 2, qq = (lane & 3) * 2;
#pragma unroll
    for (int mt = 0; mt < 4; mt++) {
        const int rl1 = wm * 64 + mt * 16 + rq, rl2 = rl1 + 8;
        const size_t r1 = rowbase + rl1;
        const uint32_t w1 = g_mbits[r1 * (SKL / 32) + kt * 4 + wn];
        const uint32_t w2 = g_mbits[(r1 + 8) * (SKL / 32) + kt * 4 + wn];
        float s1 = 0.0f, s2 = 0.0f;
#pragma unroll
        for (int nt = 0; nt < 4; nt++) {
            int cl = wn * 32 + nt * 8 + qq;
            int bit = nt * 8 + qq;
            float* c = acc[mt][nt];
            float e0 = (w1 >> bit) & 1        ? __half2float(__float2half_rn(__expf(c[0] * scale))) : 0.0f;
            float e1 = (w1 >> (bit + 1)) & 1  ? __half2float(__float2half_rn(__expf(c[1] * scale))) : 0.0f;
            float e2 = (w2 >> bit) & 1        ? __half2float(__float2half_rn(__expf(c[2] * scale))) : 0.0f;
            float e3 = (w2 >> (bit + 1)) & 1  ? __half2float(__float2half_rn(__expf(c[3] * scale))) : 0.0f;
            stashf[rl1 * STASHW + cl]     = e0;
            stashf[rl1 * STASHW + cl + 1] = e1;
            stashf[rl2 * STASHW + cl]     = e2;
            stashf[rl2 * STASHW + cl + 1] = e3;
            s1 += e0 + e1;
            s2 += e2 + e3;
        }
#pragma unroll
        for (int off = 1; off <= 2; off <<= 1) {
            s1 += __shfl_xor_sync(0xffffffffu, s1, off);
            s2 += __shfl_xor_sync(0xffffffffu, s2, off);
        }
        if ((lane & 3) == 0) {
            red2[wn * 128 + rl1] = s1;
            red2[wn * 128 + rl2] = s2;
        }
    }
    __syncthreads();
    if (tid < 128) {
        float s = red2[tid] + red2[128 + tid] + red2[256 + tid] + red2[384 + tid];
        g_ps[(rowbase + tid) * NTILES + kt] = s;
    }

    // coalesced fp16 E write
#pragma unroll
    for (int g = 0; g < 16; g++) {
        int idx = tid + g * 256;
        int r = idx >> 5, cg = idx & 31;
        float4 e = *(const float4*)&stashf[r * STASHW + cg * 4];
        size_t off = (rowbase + r) * SKL + kt * 128 + cg * 4;
        *(uint2*)(g_Ef + off) = make_uint2(pack2h(e.x, e.y), pack2h(e.z, e.w));
    }
}

// ---------------------------------------------------------------------------
// pv: ctx = (E @ (Vh+Vl)) * inv (2-term fp16); P = E * inv written coalesced
// (final attn). E/Vh/Vl staged via cp.async, TRIPLE-buffered 32-k slices.
// grid (16 qt, 16 b), 256 thr / 8 warps (m16 each), 2 CTA/SM.
// ---------------------------------------------------------------------------
__global__ __launch_bounds__(256, 2) void pv_mma_kernel(float* __restrict__ attn,
                                                        float* __restrict__ ctx) {
    extern __shared__ char sm[];
    const uint32_t sb = (uint32_t)__cvta_generic_to_shared(sm);
    const int tid = threadIdx.x, w = tid >> 5, lane = tid & 31;
    const int rq = lane >> 2, qq = (lane & 3) * 2;
    const int qt = blockIdx.x, b = blockIdx.y;
    const size_t rowbase = (size_t)b * SQL + qt * 128;
    const size_t grow1 = rowbase + w * 16 + rq;
    const size_t grow2 = grow1 + 8;

    const int la_row = lane & 15;
    const int la_k   = (lane & 16) ? 16 : 0;
    const int lb_row = (lane & 7) + ((lane & 16) ? 8 : 0);
    const int lb_k   = (lane & 8) ? 16 : 0;

    float* sInv = (float*)(sm + 3 * BUFB3);
    if (tid < 128) {
        const float* p = g_ps + (rowbase + tid) * NTILES;
        float s = 0.0f;
#pragma unroll
        for (int i = 0; i < 4; i++) {
            float4 v = *(const float4*)(p + i * 4);
            s += v.x + v.y + v.z + v.w;
        }
        sInv[tid] = 1.0f / s;
    }

    float acc[16][4];
#pragma unroll
    for (int nt = 0; nt < 16; nt++)
#pragma unroll
        for (int i = 0; i < 4; i++) acc[nt][i] = 0.0f;

    const __half* vth = g_Vth + (size_t)b * DD * SKL;
    const __half* vtl = g_Vtl + (size_t)b * DD * SKL;
    const __half* ef  = g_Ef + rowbase * SKL;

    // buffer layout per stage: E(TT) Vh(TT) Vl(TT)
    auto stage = [&](int s, int st) {
        uint32_t base = sb + (uint32_t)st * BUFB3;
#pragma unroll
        for (int g = 0; g < 2; g++) {
            int idx = tid + g * 256;
            int row = idx >> 2, c = idx & 3;
            size_t off = (size_t)row * SKL + s * 32 + c * 8;
            cpa16(base + row * TW + c * 16, ef + off);
            cpa16(base + TT + row * TW + c * 16, vth + off);
            cpa16(base + 2 * TT + row * TW + c * 16, vtl + off);
        }
        CP_COMMIT();
    };

    stage(0, 0);
    stage(1, 1);
    float inv1 = 0.0f, inv2 = 0.0f;
    for (int s = 0; s < 64; s++) {
        if (s < 62)      { stage(s + 2, (s + 2) % 3); CP_WAIT2(); }
        else if (s == 62) { CP_WAIT1(); }
        else             { CP_WAIT0(); }
        __syncthreads();
        if (s == 0) { inv1 = sInv[w * 16 + rq]; inv2 = sInv[w * 16 + rq + 8]; }

        const uint32_t base = sb + (uint32_t)(s % 3) * BUFB3;
#pragma unroll
        for (int ks = 0; ks < 2; ks++) {
            const int kb = ks * 32;
            uint32_t aa = base + (uint32_t)(w * 16 + la_row) * TW + kb + la_k;
            uint32_t a0, a1, a2, a3;
            ldsm4(a0, a1, a2, a3, aa);
#pragma unroll
            for (int ntp = 0; ntp < 8; ntp++) {
                uint32_t ba = base + TT + (uint32_t)(ntp * 16 + lb_row) * TW + kb + lb_k;
                uint32_t bh0, bh1, bh2, bh3, bl0, bl1, bl2, bl3;
                ldsm4(bh0, bh1, bh2, bh3, ba);
                ldsm4(bl0, bl1, bl2, bl3, ba + TT);
                mma_f16(acc[2 * ntp],     a0, a1, a2, a3, bh0, bh1);
                mma_f16(acc[2 * ntp],     a0, a1, a2, a3, bl0, bl1);
                mma_f16(acc[2 * ntp + 1], a0, a1, a2, a3, bh2, bh3);
                mma_f16(acc[2 * ntp + 1], a0, a1, a2, a3, bl2, bl3);
            }
        }

        // coalesced P write: P = E * inv_row
        const char* ebp = sm + (s % 3) * BUFB3;
#pragma unroll
        for (int g = 0; g < 4; g++) {
            int idx = tid + g * 256;
            int row = idx >> 3, c4 = idx & 7;
            uint2 h = *(const uint2*)(ebp + row * TW + c4 * 8);
            float2 h0 = unpack2h(h.x), h1 = unpack2h(h.y);
            float iv = sInv[row];
            float4 pv;
            pv.x = h0.x * iv;
            pv.y = h0.y * iv;
            pv.z = h1.x * iv;
            pv.w = h1.y * iv;
            *(float4*)(attn + (rowbase + row) * SKL + s * 32 + c4 * 4) = pv;
        }
        __syncthreads();
    }

    // ctx = acc * inv
#pragma unroll
    for (int nt = 0; nt < 16; nt++) {
        int cg = nt * 8 + qq;
        *(float2*)(ctx + grow1 * DD + cg) =
            make_float2(acc[nt][0] * inv1, acc[nt][1] * inv1);
        *(float2*)(ctx + grow2 * DD + cg) =
            make_float2(acc[nt][2] * inv2, acc[nt][3] * inv2);
    }
}

// ---------------------------------------------------------------------------
extern "C" void kernel_launch(void* const* d_in, const int* in_sizes, int n_in,
                              void* d_out, int out_size) {
    const float* Q    = (const float*)d_in[0];
    const float* K    = (const float*)d_in[1];
    const float* V    = (const float*)d_in[2];
    const int*   mask = (const int*)d_in[3];

    float* ctx  = (float*)d_out;
    float* attn = (float*)d_out + (size_t)BB * SQL * DD;

    static bool attr_done = false;
    if (!attr_done) {
        cudaFuncSetAttribute(qk_mma_kernel, cudaFuncAttributeMaxDynamicSharedMemorySize, DYN_QK);
        cudaFuncSetAttribute(pv_mma_kernel, cudaFuncAttributeMaxDynamicSharedMemorySize, DYN_PV);
        attr_done = true;
    }

    prep_qk_kernel<<<dim3(2048, 2), 256>>>(Q, K);
    prep_vt_kernel<<<dim3(16, BB), 256>>>(V);
    prep_mask_kernel<<<NROWS / 8, 256>>>(mask);
    qk_mma_kernel<<<dim3(16, 16, BB), 256, DYN_QK>>>(attn);
    pv_mma_kernel<<<dim3(16, BB), 256, DYN_PV>>>(attn, ctx);
}

// round 16
// speedup vs baseline: 1.0821x; 1.0821x over previous
#include <cuda_runtime.h>
#include <cuda_bf16.h>
#include <cuda_fp16.h>
#include <cstdint>
#include <math.h>

#define BB   16
#define SQL  2048
#define SKL  2048
#define DD   128
#define NROWS (BB * SQL)
#define NTILES 16

// ---------------- scratch (__device__ globals; no allocation) ----------------
__device__ __half g_Qh16[(size_t)BB * SQL * DD];         // Q hi (fp16)
__device__ __half g_Ql16[(size_t)BB * SQL * DD];         // Q lo residual (fp16)
__device__ __half g_K16[(size_t)BB * SKL * DD];          // K (fp16, single)
__device__ __half g_Vth[(size_t)BB * DD * SKL];          // V^T hi (fp16)
__device__ __half g_Vtl[(size_t)BB * DD * SKL];          // V^T lo (fp16)
__device__ __half g_Ef[(size_t)NROWS * SKL];             // exp (fp16)
__device__ float g_ps[(size_t)NROWS * NTILES];           // per-(row,ktile) sum exp

// ---------------- helpers ----------------------------------------------------
__device__ __forceinline__ uint32_t pack2h_hi(float a, float b, float& la, float& lb) {
    __half ha = __float2half_rn(a), hb = __float2half_rn(b);
    la = a - __half2float(ha);
    lb = b - __half2float(hb);
    return (uint32_t)__half_as_ushort(ha) | ((uint32_t)__half_as_ushort(hb) << 16);
}
__device__ __forceinline__ uint32_t pack2h(float a, float b) {
    __half ha = __float2half_rn(a), hb = __float2half_rn(b);
    return (uint32_t)__half_as_ushort(ha) | ((uint32_t)__half_as_ushort(hb) << 16);
}
__device__ __forceinline__ float2 unpack2h(uint32_t u) {
    __half2 v = *reinterpret_cast<__half2*>(&u);
    return make_float2(__half2float(v.x), __half2float(v.y));
}
__device__ __forceinline__ void mma_f16(float* c, uint32_t a0, uint32_t a1,
                                        uint32_t a2, uint32_t a3,
                                        uint32_t b0, uint32_t b1) {
    asm volatile(
        "mma.sync.aligned.m16n8k16.row.col.f32.f16.f16.f32 "
        "{%0,%1,%2,%3}, {%4,%5,%6,%7}, {%8,%9}, {%0,%1,%2,%3};"
        : "+f"(c[0]), "+f"(c[1]), "+f"(c[2]), "+f"(c[3])
        : "r"(a0), "r"(a1), "r"(a2), "r"(a3), "r"(b0), "r"(b1));
}
__device__ __forceinline__ void ldsm4(uint32_t& r0, uint32_t& r1, uint32_t& r2,
                                      uint32_t& r3, uint32_t addr) {
    asm volatile("ldmatrix.sync.aligned.m8n8.x4.shared.b16 {%0,%1,%2,%3}, [%4];"
                 : "=r"(r0), "=r"(r1), "=r"(r2), "=r"(r3) : "r"(addr));
}
__device__ __forceinline__ void cpa16(uint32_t dst, const void* src) {
    asm volatile("cp.async.cg.shared.global [%0], [%1], 16;" :: "r"(dst), "l"(src));
}
#define CP_COMMIT() asm volatile("cp.async.commit_group;" ::: "memory")
#define CP_WAIT0()  asm volatile("cp.async.wait_group 0;" ::: "memory")
#define CP_WAIT1()  asm volatile("cp.async.wait_group 1;" ::: "memory")
#define CP_WAIT2()  asm volatile("cp.async.wait_group 2;" ::: "memory")

// tile geometry: 128 rows x 32 cols (2B elems), row stride 80 bytes
#define TW 80
#define TT (128 * TW)                   // 10240 per tile
#define QKB (3 * TT)                    // qk: 3-tile buffer (Qh, Ql, K)
#define BUFB3 (3 * TT)                  // pv: 3-tile buffer (E, Vh, Vl)
#define STASHW 132
#define DYN_QK 69632                    // stash(67584) + red2(2048); > 2*QKB
#define DYN_PV (3 * BUFB3 + 512)        // 92672 (3-stage pipeline)

// ---------------------------------------------------------------------------
// prep: Q -> fp16 hi/lo; K -> single fp16 (row-major, linear)
// ---------------------------------------------------------------------------
__global__ __launch_bounds__(256) void prep_qk_kernel(const float* __restrict__ Q,
                                                      const float* __restrict__ K) {
    size_t idx = (size_t)blockIdx.x * 256 + threadIdx.x;
    if (blockIdx.y == 0) {
        const float* p = Q + idx * 8;
        float4 f0 = *(const float4*)p, f1 = *(const float4*)(p + 4);
        float l[8];
        uint4 hv, lv;
        hv.x = pack2h_hi(f0.x, f0.y, l[0], l[1]);
        hv.y = pack2h_hi(f0.z, f0.w, l[2], l[3]);
        hv.z = pack2h_hi(f1.x, f1.y, l[4], l[5]);
        hv.w = pack2h_hi(f1.z, f1.w, l[6], l[7]);
        lv.x = pack2h(l[0], l[1]); lv.y = pack2h(l[2], l[3]);
        lv.z = pack2h(l[4], l[5]); lv.w = pack2h(l[6], l[7]);
        *(uint4*)(g_Qh16 + idx * 8) = hv;
        *(uint4*)(g_Ql16 + idx * 8) = lv;
    } else {
        const float* p = K + idx * 8;
        float4 f0 = *(const float4*)p, f1 = *(const float4*)(p + 4);
        uint4 hv;
        hv.x = pack2h(f0.x, f0.y);
        hv.y = pack2h(f0.z, f0.w);
        hv.z = pack2h(f1.x, f1.y);
        hv.w = pack2h(f1.z, f1.w);
        *(uint4*)(g_K16 + idx * 8) = hv;
    }
}

// prep: V^T fp16 hi/lo: [b][dv][k]
__global__ __launch_bounds__(256) void prep_vt_kernel(const float* __restrict__ V) {
    int chunk = blockIdx.x, b = blockIdx.y, tid = threadIdx.x;
#pragma unroll
    for (int g = 0; g < 8; g++) {
        int item = tid + g * 256;
        int r = item & 127;           // n (dv)
        int c8 = item >> 7;           // k-group
        int k0 = chunk * 128 + c8 * 8;
        float f[8], l[8];
#pragma unroll
        for (int j = 0; j < 8; j++)
            f[j] = V[((size_t)b * SKL + k0 + j) * DD + r];
        uint4 hv, lv;
        hv.x = pack2h_hi(f[0], f[1], l[0], l[1]);
        hv.y = pack2h_hi(f[2], f[3], l[2], l[3]);
        hv.z = pack2h_hi(f[4], f[5], l[4], l[5]);
        hv.w = pack2h_hi(f[6], f[7], l[6], l[7]);
        lv.x = pack2h(l[0], l[1]); lv.y = pack2h(l[2], l[3]);
        lv.z = pack2h(l[4], l[5]); lv.w = pack2h(l[6], l[7]);
        size_t dst = ((size_t)b * DD + r) * SKL + k0;
        *(uint4*)(g_Vth + dst) = hv;
        *(uint4*)(g_Vtl + dst) = lv;
    }
}

// ---------------------------------------------------------------------------
// qk: E = exp(scale * (Qh+Ql) @ K16^T) masked (->0), fp16-quantized; writes E
// + per-(row,ktile) sums of quantized values. grid (16,16,16), 256 thr.
// ---------------------------------------------------------------------------
__global__ __launch_bounds__(256, 2) void qk_mma_kernel(const int* __restrict__ mask) {
    extern __shared__ char sm[];
    const uint32_t sb = (uint32_t)__cvta_generic_to_shared(sm);
    const int tid = threadIdx.x, wid = tid >> 5, lane = tid & 31;
    const int wm = wid >> 2, wn = wid & 3;
    const int kt = blockIdx.x, qt = blockIdx.y, b = blockIdx.z;
    const size_t rowbase = (size_t)b * SQL + qt * 128;

    const int la_row = lane & 15;
    const int la_k   = (lane & 16) ? 16 : 0;
    const int lb_row = (lane & 7) + ((lane & 16) ? 8 : 0);
    const int lb_k   = (lane & 8) ? 16 : 0;

    float acc[4][4][4];
#pragma unroll
    for (int mt = 0; mt < 4; mt++)
#pragma unroll
        for (int nt = 0; nt < 4; nt++)
#pragma unroll
            for (int i = 0; i < 4; i++) acc[mt][nt][i] = 0.0f;

    const __half* srcs[3] = {
        g_Qh16 + rowbase * DD, g_Ql16 + rowbase * DD,
        g_K16 + ((size_t)b * SKL + kt * 128) * DD};

    auto qstage = [&](int sl, int st) {
        uint32_t base = sb + (uint32_t)st * QKB;
#pragma unroll
        for (int t = 0; t < 3; t++) {
            const __half* sp = srcs[t] + sl * 32;
            uint32_t db = base + t * TT;
#pragma unroll
            for (int g = 0; g < 2; g++) {
                int idx = tid + g * 256;
                int row = idx >> 2, c = idx & 3;
                cpa16(db + row * TW + c * 16, sp + (size_t)row * DD + c * 8);
            }
        }
        CP_COMMIT();
    };

    qstage(0, 0);
#pragma unroll
    for (int sl = 0; sl < 4; sl++) {
        if (sl < 3) { qstage(sl + 1, (sl + 1) & 1); CP_WAIT1(); }
        else        { CP_WAIT0(); }
        __syncthreads();
        const uint32_t base = sb + (uint32_t)(sl & 1) * QKB;
#pragma unroll
        for (int ks = 0; ks < 2; ks++) {
            const int kb = ks * 32;
            uint32_t bk[4][2];
#pragma unroll
            for (int ntp = 0; ntp < 2; ntp++) {
                uint32_t ba = base + 2 * TT + (uint32_t)(wn * 32 + ntp * 16 + lb_row) * TW + kb + lb_k;
                ldsm4(bk[2 * ntp][0], bk[2 * ntp][1], bk[2 * ntp + 1][0], bk[2 * ntp + 1][1], ba);
            }
#pragma unroll
            for (int mt = 0; mt < 4; mt++) {
                uint32_t aa = base + (uint32_t)(wm * 64 + mt * 16 + la_row) * TW + kb + la_k;
                uint32_t ah0, ah1, ah2, ah3, al0, al1, al2, al3;
                ldsm4(ah0, ah1, ah2, ah3, aa);
                ldsm4(al0, al1, al2, al3, aa + TT);
#pragma unroll
                for (int nt = 0; nt < 4; nt++) {
                    mma_f16(acc[mt][nt], ah0, ah1, ah2, ah3, bk[nt][0], bk[nt][1]);
                    mma_f16(acc[mt][nt], al0, al1, al2, al3, bk[nt][0], bk[nt][1]);
                }
            }
        }
        __syncthreads();
    }

    // epilogue: direct mask, exp, fp16 quantize, sums, stash, fp16 write
    float* stashf = (float*)sm;
    float* red2   = (float*)(sm + 128 * STASHW * 4);   // 67584

    const float scale = 0.08838834764831845f;
    const int rq = lane >> 2, qq = (lane & 3) * 2;
#pragma unroll
    for (int mt = 0; mt < 4; mt++) {
        const int rl1 = wm * 64 + mt * 16 + rq, rl2 = rl1 + 8;
        const size_t r1 = rowbase + rl1;
        float s1 = 0.0f, s2 = 0.0f;
#pragma unroll
        for (int nt = 0; nt < 4; nt++) {
            int cl = wn * 32 + nt * 8 + qq;
            int colg = kt * 128 + cl;
            int2 m1 = *(const int2*)(mask + r1 * SKL + colg);
            int2 m2 = *(const int2*)(mask + (r1 + 8) * SKL + colg);
            float* c = acc[mt][nt];
            float e0 = m1.x ? __half2float(__float2half_rn(__expf(c[0] * scale))) : 0.0f;
            float e1 = m1.y ? __half2float(__float2half_rn(__expf(c[1] * scale))) : 0.0f;
            float e2 = m2.x ? __half2float(__float2half_rn(__expf(c[2] * scale))) : 0.0f;
            float e3 = m2.y ? __half2float(__float2half_rn(__expf(c[3] * scale))) : 0.0f;
            stashf[rl1 * STASHW + cl]     = e0;
            stashf[rl1 * STASHW + cl + 1] = e1;
            stashf[rl2 * STASHW + cl]     = e2;
            stashf[rl2 * STASHW + cl + 1] = e3;
            s1 += e0 + e1;
            s2 += e2 + e3;
        }
#pragma unroll
        for (int off = 1; off <= 2; off <<= 1) {
            s1 += __shfl_xor_sync(0xffffffffu, s1, off);
            s2 += __shfl_xor_sync(0xffffffffu, s2, off);
        }
        if ((lane & 3) == 0) {
            red2[wn * 128 + rl1] = s1;
            red2[wn * 128 + rl2] = s2;
        }
    }
    __syncthreads();
    if (tid < 128) {
        float s = red2[tid] + red2[128 + tid] + red2[256 + tid] + red2[384 + tid];
        g_ps[(rowbase + tid) * NTILES + kt] = s;
    }

    // coalesced fp16 E write
#pragma unroll
    for (int g = 0; g < 16; g++) {
        int idx = tid + g * 256;
        int r = idx >> 5, cg = idx & 31;
        float4 e = *(const float4*)&stashf[r * STASHW + cg * 4];
        size_t off = (rowbase + r) * SKL + kt * 128 + cg * 4;
        *(uint2*)(g_Ef + off) = make_uint2(pack2h(e.x, e.y), pack2h(e.z, e.w));
    }
}

// ---------------------------------------------------------------------------
// pv: ctx = (E @ (Vh+Vl)) * inv (2-term fp16); P = E * inv written coalesced
// (final attn). E/Vh/Vl staged via cp.async, TRIPLE-buffered 32-k slices.
// grid (16 qt, 16 b), 256 thr / 8 warps (m16 each), 2 CTA/SM.
// ---------------------------------------------------------------------------
__global__ __launch_bounds__(256, 2) void pv_mma_kernel(float* __restrict__ attn,
                                                        float* __restrict__ ctx) {
    extern __shared__ char sm[];
    const uint32_t sb = (uint32_t)__cvta_generic_to_shared(sm);
    const int tid = threadIdx.x, w = tid >> 5, lane = tid & 31;
    const int rq = lane >> 2, qq = (lane & 3) * 2;
    const int qt = blockIdx.x, b = blockIdx.y;
    const size_t rowbase = (size_t)b * SQL + qt * 128;
    const size_t grow1 = rowbase + w * 16 + rq;
    const size_t grow2 = grow1 + 8;

    const int la_row = lane & 15;
    const int la_k   = (lane & 16) ? 16 : 0;
    const int lb_row = (lane & 7) + ((lane & 16) ? 8 : 0);
    const int lb_k   = (lane & 8) ? 16 : 0;

    float* sInv = (float*)(sm + 3 * BUFB3);
    if (tid < 128) {
        const float* p = g_ps + (rowbase + tid) * NTILES;
        float s = 0.0f;
#pragma unroll
        for (int i = 0; i < 4; i++) {
            float4 v = *(const float4*)(p + i * 4);
            s += v.x + v.y + v.z + v.w;
        }
        sInv[tid] = 1.0f / s;
    }

    float acc[16][4];
#pragma unroll
    for (int nt = 0; nt < 16; nt++)
#pragma unroll
        for (int i = 0; i < 4; i++) acc[nt][i] = 0.0f;

    const __half* vth = g_Vth + (size_t)b * DD * SKL;
    const __half* vtl = g_Vtl + (size_t)b * DD * SKL;
    const __half* ef  = g_Ef + rowbase * SKL;

    // buffer layout per stage: E(TT) Vh(TT) Vl(TT)
    auto stage = [&](int s, int st) {
        uint32_t base = sb + (uint32_t)st * BUFB3;
#pragma unroll
        for (int g = 0; g < 2; g++) {
            int idx = tid + g * 256;
            int row = idx >> 2, c = idx & 3;
            size_t off = (size_t)row * SKL + s * 32 + c * 8;
            cpa16(base + row * TW + c * 16, ef + off);
            cpa16(base + TT + row * TW + c * 16, vth + off);
            cpa16(base + 2 * TT + row * TW + c * 16, vtl + off);
        }
        CP_COMMIT();
    };

    stage(0, 0);
    stage(1, 1);
    float inv1 = 0.0f, inv2 = 0.0f;
    for (int s = 0; s < 64; s++) {
        if (s < 62)      { stage(s + 2, (s + 2) % 3); CP_WAIT2(); }
        else if (s == 62) { CP_WAIT1(); }
        else             { CP_WAIT0(); }
        __syncthreads();
        if (s == 0) { inv1 = sInv[w * 16 + rq]; inv2 = sInv[w * 16 + rq + 8]; }

        const uint32_t base = sb + (uint32_t)(s % 3) * BUFB3;
#pragma unroll
        for (int ks = 0; ks < 2; ks++) {
            const int kb = ks * 32;
            uint32_t aa = base + (uint32_t)(w * 16 + la_row) * TW + kb + la_k;
            uint32_t a0, a1, a2, a3;
            ldsm4(a0, a1, a2, a3, aa);
#pragma unroll
            for (int ntp = 0; ntp < 8; ntp++) {
                uint32_t ba = base + TT + (uint32_t)(ntp * 16 + lb_row) * TW + kb + lb_k;
                uint32_t bh0, bh1, bh2, bh3, bl0, bl1, bl2, bl3;
                ldsm4(bh0, bh1, bh2, bh3, ba);
                ldsm4(bl0, bl1, bl2, bl3, ba + TT);
                mma_f16(acc[2 * ntp],     a0, a1, a2, a3, bh0, bh1);
                mma_f16(acc[2 * ntp],     a0, a1, a2, a3, bl0, bl1);
                mma_f16(acc[2 * ntp + 1], a0, a1, a2, a3, bh2, bh3);
                mma_f16(acc[2 * ntp + 1], a0, a1, a2, a3, bl2, bl3);
            }
        }

        // coalesced P write: P = E * inv_row
        const char* ebp = sm + (s % 3) * BUFB3;
#pragma unroll
        for (int g = 0; g < 4; g++) {
            int idx = tid + g * 256;
            int row = idx >> 3, c4 = idx & 7;
            uint2 h = *(const uint2*)(ebp + row * TW + c4 * 8);
            float2 h0 = unpack2h(h.x), h1 = unpack2h(h.y);
            float iv = sInv[row];
            float4 pv;
            pv.x = h0.x * iv;
            pv.y = h0.y * iv;
            pv.z = h1.x * iv;
            pv.w = h1.y * iv;
            *(float4*)(attn + (rowbase + row) * SKL + s * 32 + c4 * 4) = pv;
        }
        __syncthreads();
    }

    // ctx = acc * inv
#pragma unroll
    for (int nt = 0; nt < 16; nt++) {
        int cg = nt * 8 + qq;
        *(float2*)(ctx + grow1 * DD + cg) =
            make_float2(acc[nt][0] * inv1, acc[nt][1] * inv1);
        *(float2*)(ctx + grow2 * DD + cg) =
            make_float2(acc[nt][2] * inv2, acc[nt][3] * inv2);
    }
}

// ---------------------------------------------------------------------------
extern "C" void kernel_launch(void* const* d_in, const int* in_sizes, int n_in,
                              void* d_out, int out_size) {
    const float* Q    = (const float*)d_in[0];
    const float* K    = (const float*)d_in[1];
    const float* V    = (const float*)d_in[2];
    const int*   mask = (const int*)d_in[3];

    float* ctx  = (float*)d_out;
    float* attn = (float*)d_out + (size_t)BB * SQL * DD;

    static bool attr_done = false;
    if (!attr_done) {
        cudaFuncSetAttribute(qk_mma_kernel, cudaFuncAttributeMaxDynamicSharedMemorySize, DYN_QK);
        cudaFuncSetAttribute(pv_mma_kernel, cudaFuncAttributeMaxDynamicSharedMemorySize, DYN_PV);
        attr_done = true;
    }

    prep_qk_kernel<<<dim3(2048, 2), 256>>>(Q, K);
    prep_vt_kernel<<<dim3(16, BB), 256>>>(V);
    qk_mma_kernel<<<dim3(16, 16, BB), 256, DYN_QK>>>(mask);
    pv_mma_kernel<<<dim3(16, BB), 256, DYN_PV>>>(attn, ctx);
}

// round 17
// speedup vs baseline: 1.3615x; 1.2583x over previous
#include <cuda_runtime.h>
#include <cuda_bf16.h>
#include <cuda_fp16.h>
#include <cstdint>
#include <math.h>

#define BB   16
#define SQL  2048
#define SKL  2048
#define DD   128
#define NROWS (BB * SQL)
#define NTILES 16

// ---------------- scratch (__device__ globals; no allocation) ----------------
__device__ __half g_Qh16[(size_t)BB * SQL * DD];         // Q hi (fp16)
__device__ __half g_Ql16[(size_t)BB * SQL * DD];         // Q lo residual (fp16)
__device__ __half g_K16[(size_t)BB * SKL * DD];          // K (fp16, single)
__device__ __half g_Vt[(size_t)BB * DD * SKL];           // V^T (fp16, single)
__device__ __half g_Ef[(size_t)NROWS * SKL];             // exp (fp16)
__device__ float g_ps[(size_t)NROWS * NTILES];           // per-(row,ktile) sum exp

// ---------------- helpers ----------------------------------------------------
__device__ __forceinline__ uint32_t pack2h_hi(float a, float b, float& la, float& lb) {
    __half ha = __float2half_rn(a), hb = __float2half_rn(b);
    la = a - __half2float(ha);
    lb = b - __half2float(hb);
    return (uint32_t)__half_as_ushort(ha) | ((uint32_t)__half_as_ushort(hb) << 16);
}
__device__ __forceinline__ uint32_t pack2h(float a, float b) {
    __half ha = __float2half_rn(a), hb = __float2half_rn(b);
    return (uint32_t)__half_as_ushort(ha) | ((uint32_t)__half_as_ushort(hb) << 16);
}
__device__ __forceinline__ float2 unpack2h(uint32_t u) {
    __half2 v = *reinterpret_cast<__half2*>(&u);
    return make_float2(__half2float(v.x), __half2float(v.y));
}
__device__ __forceinline__ void mma_f16(float* c, uint32_t a0, uint32_t a1,
                                        uint32_t a2, uint32_t a3,
                                        uint32_t b0, uint32_t b1) {
    asm volatile(
        "mma.sync.aligned.m16n8k16.row.col.f32.f16.f16.f32 "
        "{%0,%1,%2,%3}, {%4,%5,%6,%7}, {%8,%9}, {%0,%1,%2,%3};"
        : "+f"(c[0]), "+f"(c[1]), "+f"(c[2]), "+f"(c[3])
        : "r"(a0), "r"(a1), "r"(a2), "r"(a3), "r"(b0), "r"(b1));
}
__device__ __forceinline__ void ldsm4(uint32_t& r0, uint32_t& r1, uint32_t& r2,
                                      uint32_t& r3, uint32_t addr) {
    asm volatile("ldmatrix.sync.aligned.m8n8.x4.shared.b16 {%0,%1,%2,%3}, [%4];"
                 : "=r"(r0), "=r"(r1), "=r"(r2), "=r"(r3) : "r"(addr));
}
__device__ __forceinline__ void cpa16(uint32_t dst, const void* src) {
    asm volatile("cp.async.cg.shared.global [%0], [%1], 16;" :: "r"(dst), "l"(src));
}
#define CP_COMMIT() asm volatile("cp.async.commit_group;" ::: "memory")
#define CP_WAIT0()  asm volatile("cp.async.wait_group 0;" ::: "memory")
#define CP_WAIT1()  asm volatile("cp.async.wait_group 1;" ::: "memory")
#define CP_WAIT2()  asm volatile("cp.async.wait_group 2;" ::: "memory")
#define CP_WAIT3()  asm volatile("cp.async.wait_group 3;" ::: "memory")

// tile geometry: 128 rows x 32 cols (2B elems), row stride 80 bytes
#define TW 80
#define TT (128 * TW)                   // 10240 per tile
#define QKB (3 * TT)                    // qk: 3-tile buffer (Qh, Ql, K)
#define PVB (2 * TT)                    // pv: 2-tile stage (E, V)
#define STASHW 132
#define DYN_QK 69632                    // stash(67584) + red2(2048); > 2*QKB
#define DYN_PV (4 * PVB + 512)          // 82432 (4-stage pipeline)

// ---------------------------------------------------------------------------
// prep: Q -> fp16 hi/lo; K -> single fp16 (row-major, linear)
// ---------------------------------------------------------------------------
__global__ __launch_bounds__(256) void prep_qk_kernel(const float* __restrict__ Q,
                                                      const float* __restrict__ K) {
    size_t idx = (size_t)blockIdx.x * 256 + threadIdx.x;
    if (blockIdx.y == 0) {
        const float* p = Q + idx * 8;
        float4 f0 = *(const float4*)p, f1 = *(const float4*)(p + 4);
        float l[8];
        uint4 hv, lv;
        hv.x = pack2h_hi(f0.x, f0.y, l[0], l[1]);
        hv.y = pack2h_hi(f0.z, f0.w, l[2], l[3]);
        hv.z = pack2h_hi(f1.x, f1.y, l[4], l[5]);
        hv.w = pack2h_hi(f1.z, f1.w, l[6], l[7]);
        lv.x = pack2h(l[0], l[1]); lv.y = pack2h(l[2], l[3]);
        lv.z = pack2h(l[4], l[5]); lv.w = pack2h(l[6], l[7]);
        *(uint4*)(g_Qh16 + idx * 8) = hv;
        *(uint4*)(g_Ql16 + idx * 8) = lv;
    } else {
        const float* p = K + idx * 8;
        float4 f0 = *(const float4*)p, f1 = *(const float4*)(p + 4);
        uint4 hv;
        hv.x = pack2h(f0.x, f0.y);
        hv.y = pack2h(f0.z, f0.w);
        hv.z = pack2h(f1.x, f1.y);
        hv.w = pack2h(f1.z, f1.w);
        *(uint4*)(g_K16 + idx * 8) = hv;
    }
}

// prep: V^T fp16: [b][dv][k]
__global__ __launch_bounds__(256) void prep_vt_kernel(const float* __restrict__ V) {
    int chunk = blockIdx.x, b = blockIdx.y, tid = threadIdx.x;
#pragma unroll
    for (int g = 0; g < 8; g++) {
        int item = tid + g * 256;
        int r = item & 127;           // n (dv)
        int c8 = item >> 7;           // k-group
        int k0 = chunk * 128 + c8 * 8;
        float f[8];
#pragma unroll
        for (int j = 0; j < 8; j++)
            f[j] = V[((size_t)b * SKL + k0 + j) * DD + r];
        uint4 hv;
        hv.x = pack2h(f[0], f[1]);
        hv.y = pack2h(f[2], f[3]);
        hv.z = pack2h(f[4], f[5]);
        hv.w = pack2h(f[6], f[7]);
        *(uint4*)(g_Vt + ((size_t)b * DD + r) * SKL + k0) = hv;
    }
}

// ---------------------------------------------------------------------------
// qk: E = exp(scale * (Qh+Ql) @ K16^T) masked (->0), fp16-quantized; writes E
// + per-(row,ktile) sums of quantized values. grid (16,16,16), 256 thr.
// ---------------------------------------------------------------------------
__global__ __launch_bounds__(256, 2) void qk_mma_kernel(const int* __restrict__ mask) {
    extern __shared__ char sm[];
    const uint32_t sb = (uint32_t)__cvta_generic_to_shared(sm);
    const int tid = threadIdx.x, wid = tid >> 5, lane = tid & 31;
    const int wm = wid >> 2, wn = wid & 3;
    const int kt = blockIdx.x, qt = blockIdx.y, b = blockIdx.z;
    const size_t rowbase = (size_t)b * SQL + qt * 128;

    const int la_row = lane & 15;
    const int la_k   = (lane & 16) ? 16 : 0;
    const int lb_row = (lane & 7) + ((lane & 16) ? 8 : 0);
    const int lb_k   = (lane & 8) ? 16 : 0;

    float acc[4][4][4];
#pragma unroll
    for (int mt = 0; mt < 4; mt++)
#pragma unroll
        for (int nt = 0; nt < 4; nt++)
#pragma unroll
            for (int i = 0; i < 4; i++) acc[mt][nt][i] = 0.0f;

    const __half* srcs[3] = {
        g_Qh16 + rowbase * DD, g_Ql16 + rowbase * DD,
        g_K16 + ((size_t)b * SKL + kt * 128) * DD};

    auto qstage = [&](int sl, int st) {
        uint32_t base = sb + (uint32_t)st * QKB;
#pragma unroll
        for (int t = 0; t < 3; t++) {
            const __half* sp = srcs[t] + sl * 32;
            uint32_t db = base + t * TT;
#pragma unroll
            for (int g = 0; g < 2; g++) {
                int idx = tid + g * 256;
                int row = idx >> 2, c = idx & 3;
                cpa16(db + row * TW + c * 16, sp + (size_t)row * DD + c * 8);
            }
        }
        CP_COMMIT();
    };

    qstage(0, 0);
#pragma unroll
    for (int sl = 0; sl < 4; sl++) {
        if (sl < 3) { qstage(sl + 1, (sl + 1) & 1); CP_WAIT1(); }
        else        { CP_WAIT0(); }
        __syncthreads();
        const uint32_t base = sb + (uint32_t)(sl & 1) * QKB;
#pragma unroll
        for (int ks = 0; ks < 2; ks++) {
            const int kb = ks * 32;
            uint32_t bk[4][2];
#pragma unroll
            for (int ntp = 0; ntp < 2; ntp++) {
                uint32_t ba = base + 2 * TT + (uint32_t)(wn * 32 + ntp * 16 + lb_row) * TW + kb + lb_k;
                ldsm4(bk[2 * ntp][0], bk[2 * ntp][1], bk[2 * ntp + 1][0], bk[2 * ntp + 1][1], ba);
            }
#pragma unroll
            for (int mt = 0; mt < 4; mt++) {
                uint32_t aa = base + (uint32_t)(wm * 64 + mt * 16 + la_row) * TW + kb + la_k;
                uint32_t ah0, ah1, ah2, ah3, al0, al1, al2, al3;
                ldsm4(ah0, ah1, ah2, ah3, aa);
                ldsm4(al0, al1, al2, al3, aa + TT);
#pragma unroll
                for (int nt = 0; nt < 4; nt++) {
                    mma_f16(acc[mt][nt], ah0, ah1, ah2, ah3, bk[nt][0], bk[nt][1]);
                    mma_f16(acc[mt][nt], al0, al1, al2, al3, bk[nt][0], bk[nt][1]);
                }
            }
        }
        __syncthreads();
    }

    // epilogue: direct mask, exp, fp16 quantize, sums, stash, fp16 write
    float* stashf = (float*)sm;
    float* red2   = (float*)(sm + 128 * STASHW * 4);   // 67584

    const float scale = 0.08838834764831845f;
    const int rq = lane >> 2, qq = (lane & 3) * 2;
#pragma unroll
    for (int mt = 0; mt < 4; mt++) {
        const int rl1 = wm * 64 + mt * 16 + rq, rl2 = rl1 + 8;
        const size_t r1 = rowbase + rl1;
        float s1 = 0.0f, s2 = 0.0f;
#pragma unroll
        for (int nt = 0; nt < 4; nt++) {
            int cl = wn * 32 + nt * 8 + qq;
            int colg = kt * 128 + cl;
            int2 m1 = *(const int2*)(mask + r1 * SKL + colg);
            int2 m2 = *(const int2*)(mask + (r1 + 8) * SKL + colg);
            float* c = acc[mt][nt];
            float e0 = m1.x ? __half2float(__float2half_rn(__expf(c[0] * scale))) : 0.0f;
            float e1 = m1.y ? __half2float(__float2half_rn(__expf(c[1] * scale))) : 0.0f;
            float e2 = m2.x ? __half2float(__float2half_rn(__expf(c[2] * scale))) : 0.0f;
            float e3 = m2.y ? __half2float(__float2half_rn(__expf(c[3] * scale))) : 0.0f;
            stashf[rl1 * STASHW + cl]     = e0;
            stashf[rl1 * STASHW + cl + 1] = e1;
            stashf[rl2 * STASHW + cl]     = e2;
            stashf[rl2 * STASHW + cl + 1] = e3;
            s1 += e0 + e1;
            s2 += e2 + e3;
        }
#pragma unroll
        for (int off = 1; off <= 2; off <<= 1) {
            s1 += __shfl_xor_sync(0xffffffffu, s1, off);
            s2 += __shfl_xor_sync(0xffffffffu, s2, off);
        }
        if ((lane & 3) == 0) {
            red2[wn * 128 + rl1] = s1;
            red2[wn * 128 + rl2] = s2;
        }
    }
    __syncthreads();
    if (tid < 128) {
        float s = red2[tid] + red2[128 + tid] + red2[256 + tid] + red2[384 + tid];
        g_ps[(rowbase + tid) * NTILES + kt] = s;
    }

    // coalesced fp16 E write
#pragma unroll
    for (int g = 0; g < 16; g++) {
        int idx = tid + g * 256;
        int r = idx >> 5, cg = idx & 31;
        float4 e = *(const float4*)&stashf[r * STASHW + cg * 4];
        size_t off = (rowbase + r) * SKL + kt * 128 + cg * 4;
        *(uint2*)(g_Ef + off) = make_uint2(pack2h(e.x, e.y), pack2h(e.z, e.w));
    }
}

// ---------------------------------------------------------------------------
// pv: ctx = (E @ V) * inv (single-term fp16); P = E * inv written coalesced
// (final attn). E/V staged via cp.async, 4-stage pipeline of 32-k slices.
// grid (16 qt, 16 b), 256 thr / 8 warps (m16 each), 2 CTA/SM.
// ---------------------------------------------------------------------------
__global__ __launch_bounds__(256, 2) void pv_mma_kernel(float* __restrict__ attn,
                                                        float* __restrict__ ctx) {
    extern __shared__ char sm[];
    const uint32_t sb = (uint32_t)__cvta_generic_to_shared(sm);
    const int tid = threadIdx.x, w = tid >> 5, lane = tid & 31;
    const int rq = lane >> 2, qq = (lane & 3) * 2;
    const int qt = blockIdx.x, b = blockIdx.y;
    const size_t rowbase = (size_t)b * SQL + qt * 128;
    const size_t grow1 = rowbase + w * 16 + rq;
    const size_t grow2 = grow1 + 8;

    const int la_row = lane & 15;
    const int la_k   = (lane & 16) ? 16 : 0;
    const int lb_row = (lane & 7) + ((lane & 16) ? 8 : 0);
    const int lb_k   = (lane & 8) ? 16 : 0;

    float* sInv = (float*)(sm + 4 * PVB);
    if (tid < 128) {
        const float* p = g_ps + (rowbase + tid) * NTILES;
        float s = 0.0f;
#pragma unroll
        for (int i = 0; i < 4; i++) {
            float4 v = *(const float4*)(p + i * 4);
            s += v.x + v.y + v.z + v.w;
        }
        sInv[tid] = 1.0f / s;
    }

    float acc[16][4];
#pragma unroll
    for (int nt = 0; nt < 16; nt++)
#pragma unroll
        for (int i = 0; i < 4; i++) acc[nt][i] = 0.0f;

    const __half* vt = g_Vt + (size_t)b * DD * SKL;
    const __half* ef = g_Ef + rowbase * SKL;

    // buffer layout per stage: E(TT) V(TT)
    auto stage = [&](int s, int st) {
        uint32_t base = sb + (uint32_t)st * PVB;
#pragma unroll
        for (int g = 0; g < 2; g++) {
            int idx = tid + g * 256;
            int row = idx >> 2, c = idx & 3;
            size_t off = (size_t)row * SKL + s * 32 + c * 8;
            cpa16(base + row * TW + c * 16, ef + off);
            cpa16(base + TT + row * TW + c * 16, vt + off);
        }
        CP_COMMIT();
    };

    stage(0, 0);
    stage(1, 1);
    stage(2, 2);
    float inv1 = 0.0f, inv2 = 0.0f;
    for (int s = 0; s < 64; s++) {
        if (s < 61)      { stage(s + 3, (s + 3) & 3); CP_WAIT3(); }
        else if (s == 61) { CP_WAIT2(); }
        else if (s == 62) { CP_WAIT1(); }
        else              { CP_WAIT0(); }
        __syncthreads();
        if (s == 0) { inv1 = sInv[w * 16 + rq]; inv2 = sInv[w * 16 + rq + 8]; }

        const uint32_t base = sb + (uint32_t)(s & 3) * PVB;
#pragma unroll
        for (int ks = 0; ks < 2; ks++) {
            const int kb = ks * 32;
            uint32_t aa = base + (uint32_t)(w * 16 + la_row) * TW + kb + la_k;
            uint32_t a0, a1, a2, a3;
            ldsm4(a0, a1, a2, a3, aa);
#pragma unroll
            for (int ntp = 0; ntp < 8; ntp++) {
                uint32_t ba = base + TT + (uint32_t)(ntp * 16 + lb_row) * TW + kb + lb_k;
                uint32_t b0, b1, b2, b3;
                ldsm4(b0, b1, b2, b3, ba);
                mma_f16(acc[2 * ntp],     a0, a1, a2, a3, b0, b1);
                mma_f16(acc[2 * ntp + 1], a0, a1, a2, a3, b2, b3);
            }
        }

        // coalesced P write: P = E * inv_row
        const char* ebp = sm + (s & 3) * PVB;
#pragma unroll
        for (int g = 0; g < 4; g++) {
            int idx = tid + g * 256;
            int row = idx >> 3, c4 = idx & 7;
            uint2 h = *(const uint2*)(ebp + row * TW + c4 * 8);
            float2 h0 = unpack2h(h.x), h1 = unpack2h(h.y);
            float iv = sInv[row];
            float4 pv;
            pv.x = h0.x * iv;
            pv.y = h0.y * iv;
            pv.z = h1.x * iv;
            pv.w = h1.y * iv;
            *(float4*)(attn + (rowbase + row) * SKL + s * 32 + c4 * 4) = pv;
        }
        __syncthreads();
    }

    // ctx = acc * inv
#pragma unroll
    for (int nt = 0; nt < 16; nt++) {
        int cg = nt * 8 + qq;
        *(float2*)(ctx + grow1 * DD + cg) =
            make_float2(acc[nt][0] * inv1, acc[nt][1] * inv1);
        *(float2*)(ctx + grow2 * DD + cg) =
            make_float2(acc[nt][2] * inv2, acc[nt][3] * inv2);
    }
}

// ---------------------------------------------------------------------------
extern "C" void kernel_launch(void* const* d_in, const int* in_sizes, int n_in,
                              void* d_out, int out_size) {
    const float* Q    = (const float*)d_in[0];
    const float* K    = (const float*)d_in[1];
    const float* V    = (const float*)d_in[2];
    const int*   mask = (const int*)d_in[3];

    float* ctx  = (float*)d_out;
    float* attn = (float*)d_out + (size_t)BB * SQL * DD;

    static bool attr_done = false;
    if (!attr_done) {
        cudaFuncSetAttribute(qk_mma_kernel, cudaFuncAttributeMaxDynamicSharedMemorySize, DYN_QK);
        cudaFuncSetAttribute(pv_mma_kernel, cudaFuncAttributeMaxDynamicSharedMemorySize, DYN_PV);
        attr_done = true;
    }

    prep_qk_kernel<<<dim3(2048, 2), 256>>>(Q, K);
    prep_vt_kernel<<<dim3(16, BB), 256>>>(V);
    qk_mma_kernel<<<dim3(16, 16, BB), 256, DYN_QK>>>(mask);
    pv_mma_kernel<<<dim3(16, BB), 256, DYN_PV>>>(attn, ctx);
}